// round 1
// baseline (speedup 1.0000x reference)
#include <cuda_runtime.h>

// yoloLoss: pred [B,7,7,30] f32, target [B,7,7,30] f32 -> out[3] f32
// Memory-bound streaming reduction. SMEM-staged coalesced loads (cells are
// 120B, so direct per-cell loads would be catastrophically uncoalesced),
// deterministic two-stage reduction (block partials -> single-block double sum).

#define D 30
#define TPB 128
#define CELLS_PER_BLOCK 128
#define MAX_BLOCKS 8192

__device__ float g_partials[MAX_BLOCKS * 3];

__device__ __forceinline__ float sq(float x) { return x * x; }

__global__ void __launch_bounds__(TPB)
yolo_main(const float* __restrict__ pred,
          const float* __restrict__ target,
          int n_cells)
{
    __shared__ float sp[CELLS_PER_BLOCK * D];   // 15360 B
    __shared__ float st[CELLS_PER_BLOCK * D];   // 15360 B
    __shared__ float red[TPB * 3];

    const int tid = threadIdx.x;
    const long long base = (long long)blockIdx.x * (CELLS_PER_BLOCK * D);

    // Stage both tiles coalesced as float4 (block tile = 15360 B, 16B aligned).
    {
        const float4* p4 = (const float4*)(pred + base);
        const float4* t4 = (const float4*)(target + base);
        float4* sp4 = (float4*)sp;
        float4* st4 = (float4*)st;
        const int nv = (CELLS_PER_BLOCK * D) / 4;   // 960
        #pragma unroll
        for (int i = tid; i < nv; i += TPB) {
            sp4[i] = p4[i];
            st4[i] = t4[i];
        }
    }
    __syncthreads();

    const int cell = blockIdx.x * CELLS_PER_BLOCK + tid;
    float conf = 0.f, reg = 0.f, cls = 0.f;

    if (cell < n_cells) {
        const float* p = sp + tid * D;
        const float* t = st + tid * D;

        const int ij = cell % 49;
        const float fi = (float)(ij / 7);
        const float fj = (float)(ij % 7);
        const float STEPF = (float)(1.0 / 7.0);

        const float tv4 = t[4];
        const bool obj = (tv4 > 0.f);
        const bool noobj = (tv4 == 0.f);

        // target box (shared by both IoUs)
        const float tx = t[0], ty = t[1], tw = t[2], th = t[3];
        const float a1 = fmaxf((tx + fj) * STEPF - tw * 0.5f, 0.f);
        const float b1 = fmaxf((ty + fi) * STEPF - th * 0.5f, 0.f);
        const float area_t = tw * th;

        // IoU(target, pred box k)
        auto iou_with = [&](float px, float py, float pw, float ph) -> float {
            float a2 = fmaxf((px + fj) * STEPF - pw * 0.5f, 0.f);
            float b2 = fmaxf((py + fi) * STEPF - ph * 0.5f, 0.f);
            float iw = tw + pw - (fmaxf(a1 + tw, a2 + pw) - fminf(a1, a2));
            float ih = th + ph - (fmaxf(b1 + th, b2 + ph) - fminf(b1, b2));
            bool valid = (iw > 0.f) && (ih > 0.f);
            float inter = valid ? iw * ih : 0.f;
            float uni = area_t + pw * ph - inter;
            return valid ? (inter / uni) : 0.f;
        };

        const float iou1 = iou_with(p[0], p[1], p[2], p[3]);
        const float iou2 = iou_with(p[5], p[6], p[7], p[8]);
        const bool choose1 = (iou1 > iou2);
        const float m1 = (obj && choose1 && (iou1 != 0.f)) ? 1.f : 0.f;
        const float m2 = (obj && !choose1 && (iou2 != 0.f)) ? 1.f : 0.f;

        // objectness loss
        float obj_l = m1 * sq(iou1 - p[4]) + m2 * sq(iou2 - p[9]);

        // xy loss
        float xy = m1 * (sq(t[0] - p[0]) + sq(t[1] - p[1]))
                 + m2 * (sq(t[5] - p[5]) + sq(t[6] - p[6]));

        // wh (sqrt) loss
        float wh = m1 * (sq(sqrtf(t[2]) - sqrtf(p[2])) + sq(sqrtf(t[3]) - sqrtf(p[3])))
                 + m2 * (sq(sqrtf(t[7]) - sqrtf(p[7])) + sq(sqrtf(t[8]) - sqrtf(p[8])));

        // noobj conf loss over indices 4,9,14,19,24,29
        float nl = 0.f;
        #pragma unroll
        for (int k = 4; k < 30; k += 5) { float d = t[k] - p[k]; nl += d * d; }

        // class loss over indices 10..29
        float cl = 0.f;
        #pragma unroll
        for (int k = 10; k < 30; ++k) { float d = p[k] - t[k]; cl += d * d; }

        conf = obj_l + 0.5f * (noobj ? nl : 0.f);
        reg  = 5.0f * (xy + wh);
        cls  = obj ? cl : 0.f;
    }

    // Block tree reduction (deterministic).
    red[tid]           = conf;
    red[TPB + tid]     = reg;
    red[2 * TPB + tid] = cls;
    __syncthreads();
    #pragma unroll
    for (int s = TPB / 2; s > 0; s >>= 1) {
        if (tid < s) {
            red[tid]           += red[tid + s];
            red[TPB + tid]     += red[TPB + tid + s];
            red[2 * TPB + tid] += red[2 * TPB + tid + s];
        }
        __syncthreads();
    }
    if (tid == 0) {
        g_partials[blockIdx.x * 3 + 0] = red[0];
        g_partials[blockIdx.x * 3 + 1] = red[TPB];
        g_partials[blockIdx.x * 3 + 2] = red[2 * TPB];
    }
}

__global__ void yolo_final(float* __restrict__ out, int nblk, float inv_b)
{
    const int tid = threadIdx.x;
    double c = 0.0, r = 0.0, k = 0.0;
    for (int i = tid; i < nblk; i += blockDim.x) {
        c += (double)g_partials[i * 3 + 0];
        r += (double)g_partials[i * 3 + 1];
        k += (double)g_partials[i * 3 + 2];
    }
    __shared__ double sc[256], sr[256], sk[256];
    sc[tid] = c; sr[tid] = r; sk[tid] = k;
    __syncthreads();
    #pragma unroll
    for (int s = 128; s > 0; s >>= 1) {
        if (tid < s) {
            sc[tid] += sc[tid + s];
            sr[tid] += sr[tid + s];
            sk[tid] += sk[tid + s];
        }
        __syncthreads();
    }
    if (tid == 0) {
        out[0] = (float)(sc[0] * (double)inv_b);
        out[1] = (float)(sr[0] * (double)inv_b);
        out[2] = (float)(sk[0] * (double)inv_b);
    }
}

extern "C" void kernel_launch(void* const* d_in, const int* in_sizes, int n_in,
                              void* d_out, int out_size)
{
    const float* pred   = (const float*)d_in[0];
    const float* target = (const float*)d_in[1];

    const int n_cells = in_sizes[0] / D;                 // B*7*7
    const int nblk = (n_cells + CELLS_PER_BLOCK - 1) / CELLS_PER_BLOCK;
    const float inv_b = 49.0f / (float)n_cells;          // 1/B

    yolo_main<<<nblk, TPB>>>(pred, target, n_cells);
    yolo_final<<<1, 256>>>((float*)d_out, nblk, inv_b);
}

// round 2
// speedup vs baseline: 1.3325x; 1.3325x over previous
#include <cuda_runtime.h>

// yoloLoss: pred [B,7,7,30] f32, target [B,7,7,30] f32 -> out[3] f32
// Single fused persistent kernel:
//  - grid-stride over 128-cell tiles, SMEM-staged float4 coalesced loads
//  - per-block register accumulation across tiles, one tree-reduce at end
//  - last-finished block does deterministic double-precision final sum of
//    block partials (hot in L2) and writes out[3]; resets counter for graph replay.

#define D 30
#define TPB 128
#define MAX_PART 4096

__device__ float g_partials[MAX_PART * 3];
__device__ unsigned int g_done = 0;

__device__ __forceinline__ float sq(float x) { return x * x; }

__global__ void __launch_bounds__(TPB)
yolo_fused(const float* __restrict__ pred,
           const float* __restrict__ target,
           int n_cells, int n_tiles, float inv_b,
           float* __restrict__ out)
{
    __shared__ float4 sp4s[TPB * D / 4];   // 15360 B, 16B aligned
    __shared__ float4 st4s[TPB * D / 4];   // 15360 B
    __shared__ float red[TPB * 3];
    __shared__ bool is_last;

    float* sp = (float*)sp4s;
    float* st = (float*)st4s;

    const int tid = threadIdx.x;
    const float STEPF = (float)(1.0 / 7.0);

    float conf = 0.f, reg = 0.f, cls = 0.f;

    for (int tile = blockIdx.x; tile < n_tiles; tile += gridDim.x) {
        const long long base = (long long)tile * (TPB * D);

        // Stage both tiles coalesced (float4).
        {
            const float4* p4 = (const float4*)(pred + base);
            const float4* t4 = (const float4*)(target + base);
            #pragma unroll
            for (int i = tid; i < TPB * D / 4; i += TPB) {
                sp4s[i] = p4[i];
                st4s[i] = t4[i];
            }
        }
        __syncthreads();

        const int cell = tile * TPB + tid;
        if (cell < n_cells) {
            const float* p = sp + tid * D;
            const float* t = st + tid * D;

            const int ij = cell % 49;
            const float fi = (float)(ij / 7);
            const float fj = (float)(ij % 7);

            const float tv4 = t[4];
            const bool obj = (tv4 > 0.f);
            const bool noobj = (tv4 == 0.f);

            const float tx = t[0], ty = t[1], tw = t[2], th = t[3];
            const float a1 = fmaxf((tx + fj) * STEPF - tw * 0.5f, 0.f);
            const float b1 = fmaxf((ty + fi) * STEPF - th * 0.5f, 0.f);
            const float area_t = tw * th;

            auto iou_with = [&](float px, float py, float pw, float ph) -> float {
                float a2 = fmaxf((px + fj) * STEPF - pw * 0.5f, 0.f);
                float b2 = fmaxf((py + fi) * STEPF - ph * 0.5f, 0.f);
                float iw = tw + pw - (fmaxf(a1 + tw, a2 + pw) - fminf(a1, a2));
                float ih = th + ph - (fmaxf(b1 + th, b2 + ph) - fminf(b1, b2));
                bool valid = (iw > 0.f) && (ih > 0.f);
                float inter = valid ? iw * ih : 0.f;
                float uni = area_t + pw * ph - inter;
                return valid ? (inter / uni) : 0.f;
            };

            const float iou1 = iou_with(p[0], p[1], p[2], p[3]);
            const float iou2 = iou_with(p[5], p[6], p[7], p[8]);
            const bool choose1 = (iou1 > iou2);
            const float m1 = (obj && choose1 && (iou1 != 0.f)) ? 1.f : 0.f;
            const float m2 = (obj && !choose1 && (iou2 != 0.f)) ? 1.f : 0.f;

            float obj_l = m1 * sq(iou1 - p[4]) + m2 * sq(iou2 - p[9]);

            float xy = m1 * (sq(t[0] - p[0]) + sq(t[1] - p[1]))
                     + m2 * (sq(t[5] - p[5]) + sq(t[6] - p[6]));

            float wh = m1 * (sq(sqrtf(t[2]) - sqrtf(p[2])) + sq(sqrtf(t[3]) - sqrtf(p[3])))
                     + m2 * (sq(sqrtf(t[7]) - sqrtf(p[7])) + sq(sqrtf(t[8]) - sqrtf(p[8])));

            float nl = 0.f;
            #pragma unroll
            for (int k = 4; k < 30; k += 5) { float d = t[k] - p[k]; nl += d * d; }

            float cl = 0.f;
            #pragma unroll
            for (int k = 10; k < 30; ++k) { float d = p[k] - t[k]; cl += d * d; }

            conf += obj_l + 0.5f * (noobj ? nl : 0.f);
            reg  += 5.0f * (xy + wh);
            cls  += obj ? cl : 0.f;
        }
        __syncthreads();   // smem reused next iteration
    }

    // One block-level tree reduction after all tiles.
    red[tid]           = conf;
    red[TPB + tid]     = reg;
    red[2 * TPB + tid] = cls;
    __syncthreads();
    #pragma unroll
    for (int s = TPB / 2; s > 0; s >>= 1) {
        if (tid < s) {
            red[tid]           += red[tid + s];
            red[TPB + tid]     += red[TPB + tid + s];
            red[2 * TPB + tid] += red[2 * TPB + tid + s];
        }
        __syncthreads();
    }

    if (tid == 0) {
        g_partials[blockIdx.x * 3 + 0] = red[0];
        g_partials[blockIdx.x * 3 + 1] = red[TPB];
        g_partials[blockIdx.x * 3 + 2] = red[2 * TPB];
        __threadfence();
        unsigned int old = atomicAdd(&g_done, 1u);
        is_last = (old == gridDim.x - 1);
    }
    __syncthreads();

    if (is_last) {
        // Deterministic double-precision final sum over gridDim.x partials (L2-hot).
        const int nblk = gridDim.x;
        double c = 0.0, r = 0.0, k = 0.0;
        for (int i = tid; i < nblk; i += TPB) {
            c += (double)g_partials[i * 3 + 0];
            r += (double)g_partials[i * 3 + 1];
            k += (double)g_partials[i * 3 + 2];
        }
        // Reuse staging smem (16B-aligned) as double scratch.
        double* sd = (double*)sp4s;   // needs 3*TPB*8 = 3072 B < 15360 B
        sd[tid]           = c;
        sd[TPB + tid]     = r;
        sd[2 * TPB + tid] = k;
        __syncthreads();
        #pragma unroll
        for (int s = TPB / 2; s > 0; s >>= 1) {
            if (tid < s) {
                sd[tid]           += sd[tid + s];
                sd[TPB + tid]     += sd[TPB + tid + s];
                sd[2 * TPB + tid] += sd[2 * TPB + tid + s];
            }
            __syncthreads();
        }
        if (tid == 0) {
            out[0] = (float)(sd[0]       * (double)inv_b);
            out[1] = (float)(sd[TPB]     * (double)inv_b);
            out[2] = (float)(sd[2 * TPB] * (double)inv_b);
            g_done = 0;   // reset for next graph replay
        }
    }
}

extern "C" void kernel_launch(void* const* d_in, const int* in_sizes, int n_in,
                              void* d_out, int out_size)
{
    const float* pred   = (const float*)d_in[0];
    const float* target = (const float*)d_in[1];

    const int n_cells = in_sizes[0] / D;                      // B*7*7
    const int n_tiles = (n_cells + TPB - 1) / TPB;
    int nblk = 148 * 7;                                       // one full-occupancy wave
    if (nblk > n_tiles) nblk = n_tiles;
    if (nblk > MAX_PART) nblk = MAX_PART;
    const float inv_b = 49.0f / (float)n_cells;               // 1/B

    yolo_fused<<<nblk, TPB>>>(pred, target, n_cells, n_tiles, inv_b, (float*)d_out);
}

// round 3
// speedup vs baseline: 1.4313x; 1.0742x over previous
#include <cuda_runtime.h>

// yoloLoss: pred [B,7,7,30] f32, target [B,7,7,30] f32 -> out[3] f32
// Single fused persistent kernel, balanced contiguous partition:
//  - grid = 148*6 = 888 blocks (exactly one wave at the 78-reg / 6-blocks-per-SM limit)
//  - cells split evenly across blocks in 2-cell units (keeps float4 alignment);
//    max imbalance ~0.4% instead of the 32% tile-quantization tail
//  - 128-cell smem-staged tiles inside each block's range, predicated last tile
//  - last-finished block does deterministic double-precision final sum.

#define D 30
#define TPB 128
#define MAX_PART 4096

__device__ float g_partials[MAX_PART * 3];
__device__ unsigned int g_done = 0;

__device__ __forceinline__ float sq(float x) { return x * x; }

__global__ void __launch_bounds__(TPB)
yolo_fused(const float* __restrict__ pred,
           const float* __restrict__ target,
           int pair_q, int pair_r, float inv_b,
           float* __restrict__ out)
{
    __shared__ float4 sp4s[TPB * D / 4];   // 15360 B
    __shared__ float4 st4s[TPB * D / 4];   // 15360 B
    __shared__ float red[TPB * 3];
    __shared__ bool is_last;

    float* sp = (float*)sp4s;
    float* st = (float*)st4s;

    const int tid = threadIdx.x;
    const int b = blockIdx.x;
    const float STEPF = (float)(1.0 / 7.0);

    // Balanced partition in pair units (pair = 2 cells, 240 B -> 16B-aligned base).
    const int extra      = (b < pair_r) ? b : pair_r;
    const int start_cell = 2 * (b * pair_q + extra);
    const int ncell_blk  = 2 * (pair_q + (b < pair_r ? 1 : 0));

    float conf = 0.f, reg = 0.f, cls = 0.f;

    for (int off = 0; off < ncell_blk; off += TPB) {
        const int cells = min(TPB, ncell_blk - off);
        const int nv4 = cells * D / 4;     // cells is even -> divisible by 4
        const long long base = (long long)(start_cell + off) * D;

        {
            const float4* p4 = (const float4*)(pred + base);
            const float4* t4 = (const float4*)(target + base);
            for (int i = tid; i < nv4; i += TPB) {
                sp4s[i] = p4[i];
                st4s[i] = t4[i];
            }
        }
        __syncthreads();

        if (tid < cells) {
            const float* p = sp + tid * D;
            const float* t = st + tid * D;

            const int cell = start_cell + off + tid;
            const int ij = cell % 49;
            const float fi = (float)(ij / 7);
            const float fj = (float)(ij % 7);

            const float tv4 = t[4];
            const bool obj = (tv4 > 0.f);
            const bool noobj = (tv4 == 0.f);

            const float tx = t[0], ty = t[1], tw = t[2], th = t[3];
            const float a1 = fmaxf((tx + fj) * STEPF - tw * 0.5f, 0.f);
            const float b1 = fmaxf((ty + fi) * STEPF - th * 0.5f, 0.f);
            const float area_t = tw * th;

            auto iou_with = [&](float px, float py, float pw, float ph) -> float {
                float a2 = fmaxf((px + fj) * STEPF - pw * 0.5f, 0.f);
                float b2 = fmaxf((py + fi) * STEPF - ph * 0.5f, 0.f);
                float iw = tw + pw - (fmaxf(a1 + tw, a2 + pw) - fminf(a1, a2));
                float ih = th + ph - (fmaxf(b1 + th, b2 + ph) - fminf(b1, b2));
                bool valid = (iw > 0.f) && (ih > 0.f);
                float inter = valid ? iw * ih : 0.f;
                float uni = area_t + pw * ph - inter;
                return valid ? (inter / uni) : 0.f;
            };

            const float iou1 = iou_with(p[0], p[1], p[2], p[3]);
            const float iou2 = iou_with(p[5], p[6], p[7], p[8]);
            const bool choose1 = (iou1 > iou2);
            const float m1 = (obj && choose1 && (iou1 != 0.f)) ? 1.f : 0.f;
            const float m2 = (obj && !choose1 && (iou2 != 0.f)) ? 1.f : 0.f;

            float obj_l = m1 * sq(iou1 - p[4]) + m2 * sq(iou2 - p[9]);

            float xy = m1 * (sq(t[0] - p[0]) + sq(t[1] - p[1]))
                     + m2 * (sq(t[5] - p[5]) + sq(t[6] - p[6]));

            float wh = m1 * (sq(sqrtf(t[2]) - sqrtf(p[2])) + sq(sqrtf(t[3]) - sqrtf(p[3])))
                     + m2 * (sq(sqrtf(t[7]) - sqrtf(p[7])) + sq(sqrtf(t[8]) - sqrtf(p[8])));

            float nl = 0.f;
            #pragma unroll
            for (int k = 4; k < 30; k += 5) { float d = t[k] - p[k]; nl += d * d; }

            float cl = 0.f;
            #pragma unroll
            for (int k = 10; k < 30; ++k) { float d = p[k] - t[k]; cl += d * d; }

            conf += obj_l + 0.5f * (noobj ? nl : 0.f);
            reg  += 5.0f * (xy + wh);
            cls  += obj ? cl : 0.f;
        }
        __syncthreads();   // smem reused next iteration
    }

    // Block-level tree reduction.
    red[tid]           = conf;
    red[TPB + tid]     = reg;
    red[2 * TPB + tid] = cls;
    __syncthreads();
    #pragma unroll
    for (int s = TPB / 2; s > 0; s >>= 1) {
        if (tid < s) {
            red[tid]           += red[tid + s];
            red[TPB + tid]     += red[TPB + tid + s];
            red[2 * TPB + tid] += red[2 * TPB + tid + s];
        }
        __syncthreads();
    }

    if (tid == 0) {
        g_partials[b * 3 + 0] = red[0];
        g_partials[b * 3 + 1] = red[TPB];
        g_partials[b * 3 + 2] = red[2 * TPB];
        __threadfence();
        unsigned int old = atomicAdd(&g_done, 1u);
        is_last = (old == gridDim.x - 1);
    }
    __syncthreads();

    if (is_last) {
        const int nblk = gridDim.x;
        double c = 0.0, r = 0.0, k = 0.0;
        for (int i = tid; i < nblk; i += TPB) {
            c += (double)g_partials[i * 3 + 0];
            r += (double)g_partials[i * 3 + 1];
            k += (double)g_partials[i * 3 + 2];
        }
        double* sd = (double*)sp4s;   // reuse staging smem (3*128*8 = 3072 B)
        sd[tid]           = c;
        sd[TPB + tid]     = r;
        sd[2 * TPB + tid] = k;
        __syncthreads();
        #pragma unroll
        for (int s = TPB / 2; s > 0; s >>= 1) {
            if (tid < s) {
                sd[tid]           += sd[tid + s];
                sd[TPB + tid]     += sd[TPB + tid + s];
                sd[2 * TPB + tid] += sd[2 * TPB + tid + s];
            }
            __syncthreads();
        }
        if (tid == 0) {
            out[0] = (float)(sd[0]       * (double)inv_b);
            out[1] = (float)(sd[TPB]     * (double)inv_b);
            out[2] = (float)(sd[2 * TPB] * (double)inv_b);
            g_done = 0;   // reset for next graph replay
        }
    }
}

extern "C" void kernel_launch(void* const* d_in, const int* in_sizes, int n_in,
                              void* d_out, int out_size)
{
    const float* pred   = (const float*)d_in[0];
    const float* target = (const float*)d_in[1];

    const int n_cells = in_sizes[0] / D;       // B*7*7 (even: B*49, B even)
    const int n_pairs = n_cells / 2;

    int nblk = 148 * 6;                        // one exact wave at 6 blocks/SM
    if (nblk > n_pairs) nblk = n_pairs;
    if (nblk > MAX_PART) nblk = MAX_PART;

    const int pair_q = n_pairs / nblk;
    const int pair_r = n_pairs % nblk;
    const float inv_b = 49.0f / (float)n_cells;

    yolo_fused<<<nblk, TPB>>>(pred, target, pair_q, pair_r, inv_b, (float*)d_out);
}

// round 4
// speedup vs baseline: 1.7631x; 1.2318x over previous
#include <cuda_runtime.h>
#include <cstdint>

// yoloLoss: pred [B,7,7,30] f32, target [B,7,7,30] f32 -> out[3] f32
// Double-buffered TMA (cp.async.bulk) pipeline: while a block computes tile i
// from stage s, the bulk copy for tile i+2 streams into the other stage.
// Removes the load->barrier->compute serialization that capped DRAM at 46%.
// grid = 148*3 (one wave at ~63KB smem/block), balanced pair partition,
// fused deterministic double-precision epilogue in the last-done block.

#define D 30
#define TPB 128
#define TILE 128
#define STAGES 2
#define TILE_FLOATS (TILE * D)              // 3840 floats = 15360 B per tensor
#define STAGE_FLOATS (2 * TILE_FLOATS)      // pred + target
#define DYN_SMEM_BYTES (STAGES * STAGE_FLOATS * 4)   // 61440
#define MAX_PART 4096

__device__ float g_partials[MAX_PART * 3];
__device__ unsigned int g_done = 0;

__device__ __forceinline__ float sq(float x) { return x * x; }

__device__ __forceinline__ uint32_t smem_u32(const void* p) {
    uint32_t a;
    asm("{ .reg .u64 t; cvta.to.shared.u64 t, %1; cvt.u32.u64 %0, t; }" : "=r"(a) : "l"(p));
    return a;
}

__device__ __forceinline__ void mbar_init(uint32_t mbar, uint32_t count) {
    asm volatile("mbarrier.init.shared.b64 [%0], %1;" :: "r"(mbar), "r"(count) : "memory");
}
__device__ __forceinline__ void mbar_expect_tx(uint32_t mbar, uint32_t bytes) {
    asm volatile("mbarrier.arrive.expect_tx.shared.b64 _, [%0], %1;" :: "r"(mbar), "r"(bytes) : "memory");
}
__device__ __forceinline__ void mbar_wait(uint32_t mbar, uint32_t parity) {
    uint32_t done;
    asm volatile(
        "{\n\t.reg .pred p;\n\t"
        "mbarrier.try_wait.parity.acquire.cta.shared::cta.b64 p, [%1], %2;\n\t"
        "selp.b32 %0, 1, 0, p;\n\t}"
        : "=r"(done) : "r"(mbar), "r"(parity) : "memory");
    if (!done) {
        asm volatile(
            "{\n\t.reg .pred P1;\n\t"
            "WL_%=:\n\t"
            "mbarrier.try_wait.parity.acquire.cta.shared::cta.b64 P1, [%0], %1, 0x989680;\n\t"
            "@P1 bra.uni WD_%=;\n\t"
            "bra.uni WL_%=;\n\t"
            "WD_%=:\n\t}"
            :: "r"(mbar), "r"(parity) : "memory");
    }
}
__device__ __forceinline__ void bulk_g2s(uint32_t dst_smem, const void* src_gmem,
                                         uint32_t bytes, uint32_t mbar) {
    asm volatile(
        "cp.async.bulk.shared::cta.global.mbarrier::complete_tx::bytes [%0], [%1], %2, [%3];"
        :: "r"(dst_smem), "l"(src_gmem), "r"(bytes), "r"(mbar) : "memory");
}

__global__ void __launch_bounds__(TPB)
yolo_fused(const float* __restrict__ pred,
           const float* __restrict__ target,
           int pair_q, int pair_r, float inv_b,
           float* __restrict__ out)
{
    extern __shared__ float dyn[];                 // [STAGES][pred TILE_FLOATS | targ TILE_FLOATS]
    __shared__ unsigned long long mbar_s[STAGES];
    __shared__ float red[TPB * 3];
    __shared__ bool is_last;

    const int tid = threadIdx.x;
    const int b = blockIdx.x;
    const float STEPF = (float)(1.0 / 7.0);

    // Balanced partition in pair units (pair = 2 cells -> 240B-aligned bases).
    const int extra      = (b < pair_r) ? b : pair_r;
    const int start_cell = 2 * (b * pair_q + extra);
    const int ncell_blk  = 2 * (pair_q + (b < pair_r ? 1 : 0));
    const int ntiles     = (ncell_blk + TILE - 1) / TILE;

    uint32_t mb[STAGES];
    mb[0] = smem_u32(&mbar_s[0]);
    mb[1] = smem_u32(&mbar_s[1]);

    if (tid == 0) {
        mbar_init(mb[0], 1);
        mbar_init(mb[1], 1);
    }
    __syncthreads();

    // TMA issue for one tile into a stage (elected thread only).
    auto issue = [&](int tile_i, int s) {
        const int cells = min(TILE, ncell_blk - tile_i * TILE);
        const uint32_t bytes = (uint32_t)cells * D * 4u;     // cells even -> mult of 16
        const long long gbase = (long long)(start_cell + tile_i * TILE) * D;
        const uint32_t sm_p = smem_u32(dyn + s * STAGE_FLOATS);
        const uint32_t sm_t = sm_p + TILE_FLOATS * 4u;
        mbar_expect_tx(mb[s], 2u * bytes);
        bulk_g2s(sm_p, pred + gbase, bytes, mb[s]);
        bulk_g2s(sm_t, target + gbase, bytes, mb[s]);
    };

    if (tid == 0) {
        if (ntiles > 0) issue(0, 0);
        if (ntiles > 1) issue(1, 1);
    }

    float conf = 0.f, reg = 0.f, cls = 0.f;
    int ph[STAGES] = {0, 0};

    for (int i = 0; i < ntiles; ++i) {
        const int s = i & 1;
        mbar_wait(mb[s], ph[s]);
        ph[s] ^= 1;

        const int cells = min(TILE, ncell_blk - i * TILE);
        if (tid < cells) {
            const float* p = dyn + s * STAGE_FLOATS + tid * D;
            const float* t = p + TILE_FLOATS;

            const int cell = start_cell + i * TILE + tid;
            const int ij = cell % 49;
            const float fi = (float)(ij / 7);
            const float fj = (float)(ij % 7);

            const float tv4 = t[4];
            const bool obj = (tv4 > 0.f);
            const bool noobj = (tv4 == 0.f);

            const float tx = t[0], ty = t[1], tw = t[2], th = t[3];
            const float a1 = fmaxf((tx + fj) * STEPF - tw * 0.5f, 0.f);
            const float b1 = fmaxf((ty + fi) * STEPF - th * 0.5f, 0.f);
            const float area_t = tw * th;

            auto iou_with = [&](float px, float py, float pw, float phh) -> float {
                float a2 = fmaxf((px + fj) * STEPF - pw * 0.5f, 0.f);
                float b2 = fmaxf((py + fi) * STEPF - phh * 0.5f, 0.f);
                float iw = tw + pw - (fmaxf(a1 + tw, a2 + pw) - fminf(a1, a2));
                float ih = th + phh - (fmaxf(b1 + th, b2 + phh) - fminf(b1, b2));
                bool valid = (iw > 0.f) && (ih > 0.f);
                float inter = valid ? iw * ih : 0.f;
                float uni = area_t + pw * phh - inter;
                return valid ? (inter / uni) : 0.f;
            };

            const float iou1 = iou_with(p[0], p[1], p[2], p[3]);
            const float iou2 = iou_with(p[5], p[6], p[7], p[8]);
            const bool choose1 = (iou1 > iou2);
            const float m1 = (obj && choose1 && (iou1 != 0.f)) ? 1.f : 0.f;
            const float m2 = (obj && !choose1 && (iou2 != 0.f)) ? 1.f : 0.f;

            float obj_l = m1 * sq(iou1 - p[4]) + m2 * sq(iou2 - p[9]);

            float xy = m1 * (sq(t[0] - p[0]) + sq(t[1] - p[1]))
                     + m2 * (sq(t[5] - p[5]) + sq(t[6] - p[6]));

            float wh = m1 * (sq(sqrtf(t[2]) - sqrtf(p[2])) + sq(sqrtf(t[3]) - sqrtf(p[3])))
                     + m2 * (sq(sqrtf(t[7]) - sqrtf(p[7])) + sq(sqrtf(t[8]) - sqrtf(p[8])));

            float nl = 0.f;
            #pragma unroll
            for (int k = 4; k < 30; k += 5) { float d = t[k] - p[k]; nl += d * d; }

            float cl = 0.f;
            #pragma unroll
            for (int k = 10; k < 30; ++k) { float d = p[k] - t[k]; cl += d * d; }

            conf += obj_l + 0.5f * (noobj ? nl : 0.f);
            reg  += 5.0f * (xy + wh);
            cls  += obj ? cl : 0.f;
        }
        __syncthreads();                 // all threads done reading stage s
        if (tid == 0 && i + 2 < ntiles) issue(i + 2, s);
    }

    // Block-level tree reduction.
    red[tid]           = conf;
    red[TPB + tid]     = reg;
    red[2 * TPB + tid] = cls;
    __syncthreads();
    #pragma unroll
    for (int s = TPB / 2; s > 0; s >>= 1) {
        if (tid < s) {
            red[tid]           += red[tid + s];
            red[TPB + tid]     += red[TPB + tid + s];
            red[2 * TPB + tid] += red[2 * TPB + tid + s];
        }
        __syncthreads();
    }

    if (tid == 0) {
        g_partials[b * 3 + 0] = red[0];
        g_partials[b * 3 + 1] = red[TPB];
        g_partials[b * 3 + 2] = red[2 * TPB];
        __threadfence();
        unsigned int old = atomicAdd(&g_done, 1u);
        is_last = (old == gridDim.x - 1);
    }
    __syncthreads();

    if (is_last) {
        const int nblk = gridDim.x;
        double c = 0.0, r = 0.0, k = 0.0;
        for (int i = tid; i < nblk; i += TPB) {
            c += (double)g_partials[i * 3 + 0];
            r += (double)g_partials[i * 3 + 1];
            k += (double)g_partials[i * 3 + 2];
        }
        double* sd = (double*)dyn;       // reuse staging smem (3*128*8 B)
        sd[tid]           = c;
        sd[TPB + tid]     = r;
        sd[2 * TPB + tid] = k;
        __syncthreads();
        #pragma unroll
        for (int s = TPB / 2; s > 0; s >>= 1) {
            if (tid < s) {
                sd[tid]           += sd[tid + s];
                sd[TPB + tid]     += sd[TPB + tid + s];
                sd[2 * TPB + tid] += sd[2 * TPB + tid + s];
            }
            __syncthreads();
        }
        if (tid == 0) {
            out[0] = (float)(sd[0]       * (double)inv_b);
            out[1] = (float)(sd[TPB]     * (double)inv_b);
            out[2] = (float)(sd[2 * TPB] * (double)inv_b);
            g_done = 0;                  // reset for next graph replay
        }
    }
}

extern "C" void kernel_launch(void* const* d_in, const int* in_sizes, int n_in,
                              void* d_out, int out_size)
{
    const float* pred   = (const float*)d_in[0];
    const float* target = (const float*)d_in[1];

    const int n_cells = in_sizes[0] / D;       // B*7*7 (even)
    const int n_pairs = n_cells / 2;

    int nblk = 148 * 3;                        // one wave at ~63KB smem/block
    if (nblk > n_pairs) nblk = n_pairs;
    if (nblk > MAX_PART) nblk = MAX_PART;

    const int pair_q = n_pairs / nblk;
    const int pair_r = n_pairs % nblk;
    const float inv_b = 49.0f / (float)n_cells;

    cudaFuncSetAttribute(yolo_fused, cudaFuncAttributeMaxDynamicSharedMemorySize,
                         DYN_SMEM_BYTES);
    yolo_fused<<<nblk, TPB, DYN_SMEM_BYTES>>>(pred, target, pair_q, pair_r, inv_b,
                                              (float*)d_out);
}